// round 4
// baseline (speedup 1.0000x reference)
#include <cuda_runtime.h>

// ForgetMult: h_t = f_t*x_t + (1-f_t)*h_{t-1}
// f,x: (4096, 16, 512) fp32. out[t,b,h] = h_t inclusive, h_0 = hidden_init.
//
// Single-pass chunked scan with decoupled look-back:
//   - SEQ split into CHUNKS=64 chunks of L=64 timesteps.
//   - CHANNELS=8192 split into TILES=32 tiles of 256 channels.
//   - Block (tile, chunk): 256 threads, one channel each.
//   - Phase 1: stream-load the (L x 256) slab of f,x ONCE, stage a=1-f,
//     b=f*x in smem, fold chunk composite (A,B): h_end = B + A*h_in.
//   - Phase 2: publish aggregate; look back over predecessor chunks'
//     aggregates/prefixes to obtain h_in (chunk 0 folds h_init directly).
//   - Phase 3: publish inclusive prefix, replay scan from smem, write out.
// f,x are read exactly once; out written once -> ~384MB DRAM traffic.

#define SEQ_LEN  4096
#define CHANNELS 8192
#define L        64            // timesteps per chunk
#define CHUNKS   (SEQ_LEN / L) // 64
#define TILE_CH  256           // channels per block
#define TILES    (CHANNELS / TILE_CH) // 32

// Scratch (allocation-free: __device__ globals).
__device__ float g_aggA[CHUNKS * CHANNELS];   // chunk-local prod of a
__device__ float g_aggB[CHUNKS * CHANNELS];   // chunk-local scan with h_in=0
__device__ float g_prefH[CHUNKS * CHANNELS];  // inclusive h at END of chunk
__device__ int   g_flag[CHUNKS * TILES];      // 0=none, 1=agg ready, 2=prefix ready

__global__ void reset_flags_kernel()
{
    int i = blockIdx.x * blockDim.x + threadIdx.x;
    if (i < CHUNKS * TILES) g_flag[i] = 0;
}

__global__ __launch_bounds__(TILE_CH, 1)
void forget_mult_chunked_kernel(
    const float* __restrict__ f,
    const float* __restrict__ x,
    const float* __restrict__ h0,
    float* __restrict__ out)
{
    extern __shared__ float smem[];           // sA[L*256] | sB[L*256]
    float* sA = smem;
    float* sB = smem + L * TILE_CH;

    const int tile  = blockIdx.x >> 6;        // / CHUNKS
    const int chunk = blockIdx.x & (CHUNKS - 1);
    const int tid   = threadIdx.x;
    const int c     = tile * TILE_CH + tid;
    const int t0    = chunk * L;

    const float* fp = f + (size_t)t0 * CHANNELS + c;
    const float* xp = x + (size_t)t0 * CHANNELS + c;

    // ---- Phase 1: stream load + stage to smem + fold chunk composite ----
    // Composite (A,B): h_end = B + A*h_in. Step (a_i,b_i): A'=a_i*A, B'=a_i*B+b_i.
    float Aagg = 1.0f, Bagg = 0.0f;
#pragma unroll 8
    for (int i = 0; i < L; i++) {
        float ft = __ldcs(fp + (size_t)i * CHANNELS);
        float xt = __ldcs(xp + (size_t)i * CHANNELS);
        float a = 1.0f - ft;
        float b = ft * xt;
        sA[i * TILE_CH + tid] = a;
        sB[i * TILE_CH + tid] = b;
        Aagg = Aagg * a;                // independent 4-cyc chain
        Bagg = fmaf(a, Bagg, b);        // independent 4-cyc chain
    }

    // ---- Phase 2: publish aggregate (non-first chunks), then look back ----
    float hin;
    if (chunk == 0) {
        hin = h0[c];
    } else {
        g_aggA[(size_t)chunk * CHANNELS + c] = Aagg;
        g_aggB[(size_t)chunk * CHANNELS + c] = Bagg;
        __threadfence();
        __syncthreads();
        if (tid == 0)
            *(volatile int*)&g_flag[chunk * TILES + tile] = 1;

        // Decoupled look-back (per-thread, independent per channel).
        // acc composes chunks (j, chunk-1]: h_in = accB + accA * h_end(j).
        float accA = 1.0f, accB = 0.0f;
        int j = chunk - 1;
        for (;;) {
            volatile int* flp = (volatile int*)&g_flag[j * TILES + tile];
            int fl;
            while ((fl = *flp) == 0) { }
            __threadfence();
            if (fl == 2) {
                float hj = g_prefH[(size_t)j * CHANNELS + c];
                hin = fmaf(accA, hj, accB);
                break;
            }
            // prepend chunk j's aggregate
            float aj = g_aggA[(size_t)j * CHANNELS + c];
            float bj = g_aggB[(size_t)j * CHANNELS + c];
            accB = fmaf(accA, bj, accB);
            accA = accA * aj;
            j--;  // chunk 0 always ends at flag==2, so this terminates
        }
    }

    // ---- Phase 3: publish inclusive prefix, replay scan, write out ----
    g_prefH[(size_t)chunk * CHANNELS + c] = fmaf(Aagg, hin, Bagg);
    __threadfence();
    __syncthreads();
    if (tid == 0)
        *(volatile int*)&g_flag[chunk * TILES + tile] = 2;

    float* op = out + (size_t)t0 * CHANNELS + c;
    float h = hin;
#pragma unroll 8
    for (int i = 0; i < L; i++) {
        h = fmaf(sA[i * TILE_CH + tid], h, sB[i * TILE_CH + tid]);
        __stcs(op + (size_t)i * CHANNELS, h);
    }
}

extern "C" void kernel_launch(void* const* d_in, const int* in_sizes, int n_in,
                              void* d_out, int out_size)
{
    const float* f  = (const float*)d_in[0];
    const float* x  = (const float*)d_in[1];
    const float* h0 = (const float*)d_in[2];
    float* out = (float*)d_out;

    static bool attr_set = false;
    if (!attr_set) {
        cudaFuncSetAttribute(forget_mult_chunked_kernel,
                             cudaFuncAttributeMaxDynamicSharedMemorySize,
                             2 * L * TILE_CH * (int)sizeof(float));
        attr_set = true;
    }

    reset_flags_kernel<<<(CHUNKS * TILES + 255) / 256, 256>>>();

    dim3 grid(TILES * CHUNKS);   // bid = tile*CHUNKS + chunk (chunk fastest)
    dim3 block(TILE_CH);
    size_t smem_bytes = 2 * L * TILE_CH * sizeof(float);
    forget_mult_chunked_kernel<<<grid, block, smem_bytes>>>(f, x, h0, out);
}

// round 5
// speedup vs baseline: 1.6857x; 1.6857x over previous
#include <cuda_runtime.h>

// ForgetMult: h_t = f_t*x_t + (1-f_t)*h_{t-1}
// f,x: (4096, 16, 512) fp32. out inclusive, h_0 = hidden_init.
//
// Hierarchical single-pass scan:
//   Block = 32 channels x 16 sub-chunks of 16 steps (256 timesteps/block).
//   a,b live in REGISTERS (16 pairs/thread). Block-level Hillis-Steele scan
//   combines sub-chunk composites (4KB smem). Cross-time-block coupling via
//   decoupled look-back (depth <= 15) done by warp 0 only.
// f,x read exactly once, out written once -> 384MB DRAM traffic.

#define SEQ_LEN  4096
#define CHANNELS 8192
#define SL       16                     // steps per thread
#define SUBS     16                     // sub-chunks per block
#define TILE_CH  32                     // channels per block
#define TB       (SL * SUBS)            // 256 timesteps per block
#define TBLKS    (SEQ_LEN / TB)         // 16
#define TILES    (CHANNELS / TILE_CH)   // 256
#define NTHREADS (TILE_CH * SUBS)       // 512

__device__ float g_aggA[TBLKS * CHANNELS];
__device__ float g_aggB[TBLKS * CHANNELS];
__device__ float g_prefH[TBLKS * CHANNELS];
__device__ int   g_flag[TBLKS * TILES];   // 0=none 1=agg 2=prefix

__global__ void reset_flags_kernel()
{
    int i = blockIdx.x * blockDim.x + threadIdx.x;
    if (i < TBLKS * TILES) g_flag[i] = 0;
}

__global__ __launch_bounds__(NTHREADS, 2)
void forget_mult_hier_kernel(
    const float* __restrict__ f,
    const float* __restrict__ x,
    const float* __restrict__ h0,
    float* __restrict__ out)
{
    __shared__ float sA[SUBS * TILE_CH];
    __shared__ float sB[SUBS * TILE_CH];
    __shared__ float sHin[TILE_CH];

    const int tid  = threadIdx.x;
    const int c    = tid & (TILE_CH - 1);       // channel within tile
    const int s    = tid >> 5;                  // sub-chunk index (warp id)
    const int tile = blockIdx.x >> 4;           // / TBLKS
    const int tblk = blockIdx.x & (TBLKS - 1);  // time-block (fastest in bid)

    const int cg = tile * TILE_CH + c;          // global channel
    const int t0 = tblk * TB + s * SL;          // this thread's first step

    // ---- Phase 1: load 16 steps into registers, fold local composite ----
    const float* fp = f + (size_t)t0 * CHANNELS + cg;
    const float* xp = x + (size_t)t0 * CHANNELS + cg;
    float ra[SL], rb[SL];
    float cA = 1.0f, cB = 0.0f;     // h_end = cB + cA*h_in over this sub-chunk
#pragma unroll
    for (int i = 0; i < SL; i++) {
        float ft = __ldcs(fp + (size_t)i * CHANNELS);
        float xt = __ldcs(xp + (size_t)i * CHANNELS);
        float a = 1.0f - ft;
        float b = ft * xt;
        ra[i] = a; rb[i] = b;
        cB = fmaf(a, cB, b);
        cA *= a;
    }

    // ---- Phase 2: block scan over sub-chunks (Hillis-Steele, per channel) ----
    sA[s * TILE_CH + c] = cA;
    sB[s * TILE_CH + c] = cB;
    __syncthreads();
#pragma unroll
    for (int d = 1; d < SUBS; d <<= 1) {
        float pA = 1.0f, pB = 0.0f;
        if (s >= d) {
            pA = sA[(s - d) * TILE_CH + c];
            pB = sB[(s - d) * TILE_CH + c];
        }
        __syncthreads();
        if (s >= d) {
            // prepend earlier composite (pA,pB): new = cur ∘ prev
            cB = fmaf(cA, pB, cB);
            cA = cA * pA;
            sA[s * TILE_CH + c] = cA;
            sB[s * TILE_CH + c] = cB;
        }
        __syncthreads();
    }
    // cA,cB now = inclusive prefix over sub-chunks [0..s] for this channel.
    // Exclusive prefix for phase 4:
    float exA = 1.0f, exB = 0.0f;
    if (s > 0) {
        exA = sA[(s - 1) * TILE_CH + c];
        exB = sB[(s - 1) * TILE_CH + c];
    }

    // ---- Phase 3: cross-block look-back (warp 0 only, depth <= 15) ----
    if (tid < TILE_CH) {
        const float blkA = sA[(SUBS - 1) * TILE_CH + tid];
        const float blkB = sB[(SUBS - 1) * TILE_CH + tid];
        const int   cg0  = tile * TILE_CH + tid;
        float hin_blk;
        if (tblk == 0) {
            hin_blk = h0[cg0];
        } else {
            g_aggA[(size_t)tblk * CHANNELS + cg0] = blkA;
            g_aggB[(size_t)tblk * CHANNELS + cg0] = blkB;
            __threadfence();
            __syncwarp(0xFFFFFFFFu);
            if (tid == 0)
                *(volatile int*)&g_flag[tblk * TILES + tile] = 1;

            float accA = 1.0f, accB = 0.0f;
            int j = tblk - 1;
            for (;;) {
                int fl;
                do { fl = *(volatile int*)&g_flag[j * TILES + tile]; } while (fl == 0);
                __threadfence();
                if (fl == 2) {
                    float hj = g_prefH[(size_t)j * CHANNELS + cg0];
                    hin_blk = fmaf(accA, hj, accB);
                    break;
                }
                float aj = g_aggA[(size_t)j * CHANNELS + cg0];
                float bj = g_aggB[(size_t)j * CHANNELS + cg0];
                accB = fmaf(accA, bj, accB);
                accA *= aj;
                j--;   // tblk 0 always reaches state 2 -> terminates
            }
        }
        g_prefH[(size_t)tblk * CHANNELS + cg0] = fmaf(blkA, hin_blk, blkB);
        __threadfence();
        __syncwarp(0xFFFFFFFFu);
        if (tid == 0)
            *(volatile int*)&g_flag[tblk * TILES + tile] = 2;
        sHin[tid] = hin_blk;
    }
    __syncthreads();

    // ---- Phase 4: replay from registers, write out ----
    float h = fmaf(exA, sHin[c], exB);   // h entering this thread's sub-chunk
    float* op = out + (size_t)t0 * CHANNELS + cg;
#pragma unroll
    for (int i = 0; i < SL; i++) {
        h = fmaf(ra[i], h, rb[i]);
        __stcs(op + (size_t)i * CHANNELS, h);
    }
}

extern "C" void kernel_launch(void* const* d_in, const int* in_sizes, int n_in,
                              void* d_out, int out_size)
{
    const float* f  = (const float*)d_in[0];
    const float* x  = (const float*)d_in[1];
    const float* h0 = (const float*)d_in[2];
    float* out = (float*)d_out;

    reset_flags_kernel<<<(TBLKS * TILES + 255) / 256, 256>>>();

    dim3 grid(TILES * TBLKS);   // tblk fastest-varying -> predecessors have lower bid
    dim3 block(NTHREADS);
    forget_mult_hier_kernel<<<grid, block>>>(f, x, h0, out);
}